// round 4
// baseline (speedup 1.0000x reference)
#include <cuda_runtime.h>
#include <cuda_bf16.h>
#include <stdint.h>

#define P_PTS   10000
#define NPTS    100
#define MAXB    4096

// ------------------------------ scratch ------------------------------------
__device__ float g_phi[MAXB * 300];      // foveated points (B,300)
__device__ float g_h  [MAXB * 256];      // hidden concat [phi_out | l_out]
__device__ float g_W1t[300 * 128];       // W1 transposed: [k][c]
__device__ float g_Wct[256 * 256];       // [W3|W4] transposed: [k][j]
__device__ float g_b34[256];             // b3 + b4

// ------------------------------ f32x2 helpers -------------------------------
__device__ __forceinline__ unsigned long long pack2(float lo, float hi) {
    unsigned long long r;
    asm("mov.b64 %0, {%1, %2};" : "=l"(r) : "f"(lo), "f"(hi));
    return r;
}
__device__ __forceinline__ unsigned long long dup2(float a) {
    unsigned long long r;
    asm("mov.b64 %0, {%1, %1};" : "=l"(r) : "f"(a));
    return r;
}
__device__ __forceinline__ void ffma2(unsigned long long& acc,
                                      unsigned long long a,
                                      unsigned long long b) {
    asm("fma.rn.f32x2 %0, %1, %2, %3;" : "=l"(acc) : "l"(a), "l"(b), "l"(acc));
}
__device__ __forceinline__ float2 unpack2(unsigned long long v) {
    float2 f;
    asm("mov.b64 {%0, %1}, %2;" : "=f"(f.x), "=f"(f.y) : "l"(v));
    return f;
}

// ------------------------------ foveate (+ folded prep) ---------------------
// One CTA per batch, 512 threads, 2048-point chunks. Ordered block prefix-sum
// of the in-box mask; early exit once 100 in-box points are collected.
// Prep (weight transposes) is folded in: each global thread does <=1 element.
__global__ void foveate_kernel(const float* __restrict__ x,
                               const float* __restrict__ lt,
                               const float* __restrict__ W1,
                               const float* __restrict__ W3,
                               const float* __restrict__ W4,
                               const float* __restrict__ b3,
                               const float* __restrict__ b4) {
    int b = blockIdx.x;
    int tid = threadIdx.x, lane = tid & 31, wid = tid >> 5;

    // ---- folded prep (independent of foveation; consumed by next kernel) ----
    {
        int g = b * 512 + tid;
        if (g < 300 * 128) {
            int k = g / 128, c = g - k * 128;
            g_W1t[g] = W1[c * 300 + k];
        }
        if (g < 256 * 256) {
            int k = g >> 8, j = g & 255;
            g_Wct[g] = (k < 128) ? W3[j * 128 + k] : W4[j * 128 + (k - 128)];
        }
        if (g < 256) g_b34[g] = b3[g] + b4[g];
    }

    const float* xb = x + (size_t)b * 3 * P_PTS;
    float l0 = lt[b * 3 + 0], l1 = lt[b * 3 + 1], l2 = lt[b * 3 + 2];
    float lo0 = l0 - 0.25f, hi0 = l0 + 0.25f;
    float lo1 = l1 - 0.25f, hi1 = l1 + 0.25f;
    float lo2 = l2 - 0.25f, hi2 = l2 + 0.25f;

    __shared__ float s0[NPTS], s1[NPTS], s2[NPTS];
    __shared__ int warp_cnt[16];
    __shared__ int s_run;

    if (tid == 0) s_run = 0;
    __syncthreads();

    for (int base = 0; base < P_PTS; base += 2048) {
        int p0 = base + tid * 4;
        float v0[4], v1[4], v2[4];
        unsigned m = 0;
        if (p0 < P_PTS) {  // P divisible by 4 -> float4 fully in or out
            float4 f0 = *(const float4*)(xb + p0);
            float4 f1 = *(const float4*)(xb + P_PTS + p0);
            float4 f2 = *(const float4*)(xb + 2 * P_PTS + p0);
            v0[0]=f0.x; v0[1]=f0.y; v0[2]=f0.z; v0[3]=f0.w;
            v1[0]=f1.x; v1[1]=f1.y; v1[2]=f1.z; v1[3]=f1.w;
            v2[0]=f2.x; v2[1]=f2.y; v2[2]=f2.z; v2[3]=f2.w;
#pragma unroll
            for (int i = 0; i < 4; i++) {
                bool in = (v0[i] >= lo0) && (v0[i] <= hi0) &&
                          (v1[i] >= lo1) && (v1[i] <= hi1) &&
                          (v2[i] >= lo2) && (v2[i] <= hi2);
                m |= ((unsigned)in) << i;
            }
        }
        int cnt = __popc(m);
        int incl = cnt;
#pragma unroll
        for (int off = 1; off < 32; off <<= 1) {
            int t = __shfl_up_sync(0xffffffffu, incl, off);
            if (lane >= off) incl += t;
        }
        if (lane == 31) warp_cnt[wid] = incl;
        __syncthreads();

        int run0 = s_run;
        int woff = 0;
#pragma unroll
        for (int w = 0; w < 16; w++) woff += (w < wid) ? warp_cnt[w] : 0;
        int r = run0 + woff + (incl - cnt);
#pragma unroll
        for (int i = 0; i < 4; i++) {
            if (m & (1u << i)) {
                if (r < NPTS) { s0[r] = v0[i]; s1[r] = v1[i]; s2[r] = v2[i]; }
                r++;
            }
        }
        __syncthreads();
        if (tid == 0) {
            int tot = 0;
#pragma unroll
            for (int w = 0; w < 16; w++) tot += warp_cnt[w];
            s_run = run0 + tot;
        }
        __syncthreads();
        if (s_run >= NPTS) break;   // uniform branch (shared value)
    }

    int n = s_run;
    for (int t = tid; t < 300; t += 512) {
        int axis = t / 100, pos = t - axis * 100;
        float v = 0.0f;
        if (n > 0) {
            int j = (n >= NPTS) ? pos : (pos % n);
            v = (axis == 0) ? s0[j] : ((axis == 1) ? s1[j] : s2[j]);
        }
        g_phi[(size_t)b * 300 + t] = v;
    }
}

// ------------------------------ hidden layer --------------------------------
// h[:, :128]  = relu(phi @ W1^T + b1)   (K=300 GEMM, BM=16, BN=128, BK=20)
// h[:, 128:]  = relu(l   @ W2^T + b2)   (K=3, computed directly)
// 128 threads; thread tile 4x4; f32x2 packed math; k-unrolled float4 A loads.
__global__ void hidden_kernel(const float* __restrict__ lt,
                              const float* __restrict__ b1,
                              const float* __restrict__ W2,
                              const float* __restrict__ b2) {
    __shared__ __align__(16) float phi_s[16 * 304];
    __shared__ __align__(16) float Bs[20 * 128];
    __shared__ float ls[16 * 3];

    int row0 = blockIdx.x * 16;
    int tid = threadIdx.x, tx = tid & 31, ty = tid >> 5;

    for (int idx = tid; idx < 16 * 300; idx += 128) {
        int r = idx / 300, k = idx - r * 300;
        phi_s[r * 304 + k] = g_phi[(size_t)(row0 + r) * 300 + k];
    }
    if (tid < 48) ls[tid] = lt[row0 * 3 + tid];

    float4 bb = *(const float4*)(b1 + tx * 4);
    unsigned long long acc2[4][2];
#pragma unroll
    for (int i = 0; i < 4; i++) {
        acc2[i][0] = pack2(bb.x, bb.y);
        acc2[i][1] = pack2(bb.z, bb.w);
    }
    __syncthreads();

    for (int k0 = 0; k0 < 300; k0 += 20) {
        for (int idx = tid; idx < 20 * 128; idx += 128)
            Bs[idx] = g_W1t[k0 * 128 + idx];
        __syncthreads();
#pragma unroll
        for (int kk = 0; kk < 20; kk += 4) {
            float4 a4[4];
#pragma unroll
            for (int i = 0; i < 4; i++)
                a4[i] = *(const float4*)&phi_s[(ty * 4 + i) * 304 + k0 + kk];
#pragma unroll
            for (int q = 0; q < 4; q++) {
                float4 bq = *(const float4*)&Bs[(kk + q) * 128 + tx * 4];
                unsigned long long b01 = pack2(bq.x, bq.y);
                unsigned long long b23 = pack2(bq.z, bq.w);
#pragma unroll
                for (int i = 0; i < 4; i++) {
                    float av = (q == 0) ? a4[i].x : (q == 1) ? a4[i].y
                             : (q == 2) ? a4[i].z : a4[i].w;
                    unsigned long long aa = dup2(av);
                    ffma2(acc2[i][0], aa, b01);
                    ffma2(acc2[i][1], aa, b23);
                }
            }
        }
        __syncthreads();
    }

#pragma unroll
    for (int i = 0; i < 4; i++) {
        int r = row0 + ty * 4 + i;
        float2 p0 = unpack2(acc2[i][0]);
        float2 p1 = unpack2(acc2[i][1]);
        float4 o;
        o.x = fmaxf(p0.x, 0.f); o.y = fmaxf(p0.y, 0.f);
        o.z = fmaxf(p1.x, 0.f); o.w = fmaxf(p1.y, 0.f);
        *(float4*)&g_h[(size_t)r * 256 + tx * 4] = o;
    }

    // l_out half: one column per thread, all 16 rows. Coalesced stores.
    {
        int c = tid;  // 0..127
        float w0 = W2[c * 3 + 0], w1 = W2[c * 3 + 1], w2 = W2[c * 3 + 2];
        float bc = b2[c];
#pragma unroll 4
        for (int r = 0; r < 16; r++) {
            float v = bc + ls[r * 3 + 0] * w0 + ls[r * 3 + 1] * w1 + ls[r * 3 + 2] * w2;
            g_h[(size_t)(row0 + r) * 256 + 128 + c] = fmaxf(v, 0.f);
        }
    }
}

// ------------------------------ output layer --------------------------------
// out = relu(h @ Wc^T + b34), K=256, BM=16, BN=128, BK=16, grid (B/16, 2)
// 128 threads; thread tile 4x4; f32x2; k-unrolled float4 A loads.
__global__ void out_kernel(float* __restrict__ out) {
    __shared__ __align__(16) float hs[16 * 256];
    __shared__ __align__(16) float Bs[16 * 128];

    int row0 = blockIdx.x * 16, col0 = blockIdx.y * 128;
    int tid = threadIdx.x, tx = tid & 31, ty = tid >> 5;

    for (int idx = tid; idx < 16 * 256; idx += 128)
        hs[idx] = g_h[(size_t)row0 * 256 + idx];

    float4 bb = *(const float4*)&g_b34[col0 + tx * 4];
    unsigned long long acc2[4][2];
#pragma unroll
    for (int i = 0; i < 4; i++) {
        acc2[i][0] = pack2(bb.x, bb.y);
        acc2[i][1] = pack2(bb.z, bb.w);
    }
    __syncthreads();

    for (int k0 = 0; k0 < 256; k0 += 16) {
        for (int idx = tid; idx < 16 * 128; idx += 128) {
            int kk = idx >> 7, c = idx & 127;
            Bs[idx] = g_Wct[(k0 + kk) * 256 + col0 + c];
        }
        __syncthreads();
#pragma unroll
        for (int kk = 0; kk < 16; kk += 4) {
            float4 a4[4];
#pragma unroll
            for (int i = 0; i < 4; i++)
                a4[i] = *(const float4*)&hs[(ty * 4 + i) * 256 + k0 + kk];
#pragma unroll
            for (int q = 0; q < 4; q++) {
                float4 bq = *(const float4*)&Bs[(kk + q) * 128 + tx * 4];
                unsigned long long b01 = pack2(bq.x, bq.y);
                unsigned long long b23 = pack2(bq.z, bq.w);
#pragma unroll
                for (int i = 0; i < 4; i++) {
                    float av = (q == 0) ? a4[i].x : (q == 1) ? a4[i].y
                             : (q == 2) ? a4[i].z : a4[i].w;
                    unsigned long long aa = dup2(av);
                    ffma2(acc2[i][0], aa, b01);
                    ffma2(acc2[i][1], aa, b23);
                }
            }
        }
        __syncthreads();
    }

#pragma unroll
    for (int i = 0; i < 4; i++) {
        int r = row0 + ty * 4 + i;
        float2 p0 = unpack2(acc2[i][0]);
        float2 p1 = unpack2(acc2[i][1]);
        float4 o;
        o.x = fmaxf(p0.x, 0.f); o.y = fmaxf(p0.y, 0.f);
        o.z = fmaxf(p1.x, 0.f); o.w = fmaxf(p1.y, 0.f);
        *(float4*)&out[(size_t)r * 256 + col0 + tx * 4] = o;
    }
}

// ------------------------------ launch --------------------------------------
extern "C" void kernel_launch(void* const* d_in, const int* in_sizes, int n_in,
                              void* d_out, int out_size) {
    const float* x  = (const float*)d_in[0];
    const float* lt = (const float*)d_in[1];
    const float* W1 = (const float*)d_in[2];
    const float* b1 = (const float*)d_in[3];
    const float* W2 = (const float*)d_in[4];
    const float* b2 = (const float*)d_in[5];
    const float* W3 = (const float*)d_in[6];
    const float* b3 = (const float*)d_in[7];
    const float* W4 = (const float*)d_in[8];
    const float* b4 = (const float*)d_in[9];
    float* out = (float*)d_out;

    int B = in_sizes[0] / (3 * P_PTS);
    if (B > MAXB) B = MAXB;

    foveate_kernel<<<B, 512>>>(x, lt, W1, W3, W4, b3, b4);
    hidden_kernel<<<B / 16, 128>>>(lt, b1, W2, b2);
    out_kernel<<<dim3(B / 16, 2), 128>>>(out);
}

// round 5
// speedup vs baseline: 1.7977x; 1.7977x over previous
#include <cuda_runtime.h>
#include <cuda_bf16.h>
#include <stdint.h>

#define P_PTS   10000
#define NPTS    100
#define MAXB    4096

typedef unsigned long long ull;

// ------------------------------ scratch ------------------------------------
__device__ float g_phi[MAXB * 300];      // foveated points (B,300)
__device__ float g_h  [MAXB * 256];      // hidden concat [phi_out | l_out]
__device__ float g_W1t[304 * 128];       // W1 transposed: [k][c] (300 used)
__device__ float g_Wct[256 * 256];       // [W3|W4] transposed: [k][j]
__device__ float g_b34[256];             // b3 + b4

// ------------------------------ f32x2 helpers -------------------------------
union F4U2 { float4 f4; ull u2[2]; float f[4]; };

__device__ __forceinline__ ull pack2(float lo, float hi) {
    ull r;
    asm("mov.b64 %0, {%1, %2};" : "=l"(r) : "f"(lo), "f"(hi));
    return r;
}
__device__ __forceinline__ ull dup2(float a) {
    ull r;
    asm("mov.b64 %0, {%1, %1};" : "=l"(r) : "f"(a));
    return r;
}
__device__ __forceinline__ void ffma2(ull& acc, ull a, ull b) {
    asm("fma.rn.f32x2 %0, %1, %2, %3;" : "=l"(acc) : "l"(a), "l"(b), "l"(acc));
}
__device__ __forceinline__ float2 unpack2(ull v) {
    float2 f;
    asm("mov.b64 {%0, %1}, %2;" : "=f"(f.x), "=f"(f.y) : "l"(v));
    return f;
}

// ------------------------------ foveate (+ folded prep) ---------------------
// One CTA per batch, 512 threads, 2048-point chunks. Ballot-based ordered
// block compaction, ONE __syncthreads per chunk, early exit at 100 points.
__global__ void foveate_kernel(const float* __restrict__ x,
                               const float* __restrict__ lt,
                               const float* __restrict__ W1,
                               const float* __restrict__ W3,
                               const float* __restrict__ W4,
                               const float* __restrict__ b3,
                               const float* __restrict__ b4) {
    int b = blockIdx.x;
    int tid = threadIdx.x, lane = tid & 31, wid = tid >> 5;

    // ---- folded prep (independent work; consumed by later kernels) ----
    {
        int g = b * 512 + tid;
        if (g < 300 * 128) {
            int k = g / 128, c = g - k * 128;
            g_W1t[g] = W1[c * 300 + k];
        }
        if (g < 256 * 256) {
            int k = g >> 8, j = g & 255;
            g_Wct[g] = (k < 128) ? W3[j * 128 + k] : W4[j * 128 + (k - 128)];
        }
        if (g < 256) g_b34[g] = b3[g] + b4[g];
    }

    const float* xb = x + (size_t)b * 3 * P_PTS;
    float l0 = lt[b * 3 + 0], l1 = lt[b * 3 + 1], l2 = lt[b * 3 + 2];
    float lo0 = l0 - 0.25f, hi0 = l0 + 0.25f;
    float lo1 = l1 - 0.25f, hi1 = l1 + 0.25f;
    float lo2 = l2 - 0.25f, hi2 = l2 + 0.25f;

    __shared__ float s0[NPTS], s1[NPTS], s2[NPTS];
    __shared__ int warp_cnt[2][16];

    int run = 0, buf = 0;

    for (int base = 0; base < P_PTS; base += 2048) {
        int p0 = base + tid * 4;
        float v0[4], v1[4], v2[4];
        unsigned m = 0;
        if (p0 < P_PTS) {  // P divisible by 4 -> float4 fully in or out
            float4 f0 = *(const float4*)(xb + p0);
            float4 f1 = *(const float4*)(xb + P_PTS + p0);
            float4 f2 = *(const float4*)(xb + 2 * P_PTS + p0);
            v0[0]=f0.x; v0[1]=f0.y; v0[2]=f0.z; v0[3]=f0.w;
            v1[0]=f1.x; v1[1]=f1.y; v1[2]=f1.z; v1[3]=f1.w;
            v2[0]=f2.x; v2[1]=f2.y; v2[2]=f2.z; v2[3]=f2.w;
#pragma unroll
            for (int i = 0; i < 4; i++) {
                bool in = (v0[i] >= lo0) && (v0[i] <= hi0) &&
                          (v1[i] >= lo1) && (v1[i] <= hi1) &&
                          (v2[i] >= lo2) && (v2[i] <= hi2);
                m |= ((unsigned)in) << i;
            }
        }
        // ballot-based ordered scan (points of thread t precede thread t+1)
        unsigned bl0 = __ballot_sync(0xffffffffu, m & 1u);
        unsigned bl1 = __ballot_sync(0xffffffffu, (m >> 1) & 1u);
        unsigned bl2 = __ballot_sync(0xffffffffu, (m >> 2) & 1u);
        unsigned bl3 = __ballot_sync(0xffffffffu, (m >> 3) & 1u);
        if (lane == 0)
            warp_cnt[buf][wid] = __popc(bl0) + __popc(bl1) + __popc(bl2) + __popc(bl3);
        unsigned ltm = (1u << lane) - 1u;
        int excl = __popc(bl0 & ltm) + __popc(bl1 & ltm) +
                   __popc(bl2 & ltm) + __popc(bl3 & ltm);
        __syncthreads();

        int woff = 0, tot = 0;
#pragma unroll
        for (int w = 0; w < 16; w++) {
            int v = warp_cnt[buf][w];
            tot += v;
            if (w < wid) woff += v;
        }
        int r = run + woff + excl;
#pragma unroll
        for (int i = 0; i < 4; i++) {
            if ((m >> i) & 1u) {
                if (r < NPTS) { s0[r] = v0[i]; s1[r] = v1[i]; s2[r] = v2[i]; }
                r++;
            }
        }
        run += tot;            // identical in every thread -> uniform break
        buf ^= 1;
        if (run >= NPTS) break;
    }
    __syncthreads();           // scatter visible to all

    int n = run;
    for (int t = tid; t < 300; t += 512) {
        int axis = t / 100, pos = t - axis * 100;
        float v = 0.0f;
        if (n > 0) {
            int j = (n >= NPTS) ? pos : (pos % n);
            v = (axis == 0) ? s0[j] : ((axis == 1) ? s1[j] : s2[j]);
        }
        g_phi[(size_t)b * 300 + t] = v;
    }
}

// ------------------------------ hidden layer --------------------------------
// h[:, :128] = relu(phi @ W1^T + b1)  BM=16, BN=128, BK=20, 128 thr, 4x4 f32x2
// h[:, 128:] = relu(l @ W2^T + b2)    K=3, one column per thread
__global__ void __launch_bounds__(128)
hidden_kernel(const float* __restrict__ lt,
              const float* __restrict__ b1,
              const float* __restrict__ W2,
              const float* __restrict__ b2) {
    __shared__ __align__(16) float phi_s[16 * 304];
    __shared__ __align__(16) float Bs[2][20 * 128];
    __shared__ float ls[48];

    int row0 = blockIdx.x * 16;
    int tid = threadIdx.x, tx = tid & 31, ty = tid >> 5;

    for (int idx = tid; idx < 16 * 300; idx += 128) {
        int r = idx / 300, k = idx - r * 300;
        phi_s[r * 304 + k] = g_phi[(size_t)(row0 + r) * 300 + k];
    }
    if (tid < 48) ls[tid] = lt[row0 * 3 + tid];

    // fill Bs[0] with tile 0 (640 float4 per tile, 5 per thread)
    {
        const float4* src = (const float4*)g_W1t;
        float4* dst = (float4*)Bs[0];
#pragma unroll
        for (int i = 0; i < 5; i++) dst[i * 128 + tid] = src[i * 128 + tid];
    }

    float4 bb = *(const float4*)(b1 + tx * 4);
    ull acc[4][2];
#pragma unroll
    for (int i = 0; i < 4; i++) {
        acc[i][0] = pack2(bb.x, bb.y);
        acc[i][1] = pack2(bb.z, bb.w);
    }

    for (int kt = 0; kt < 15; kt++) {
        __syncthreads();
        int cur = kt & 1;
        // register prefetch of next tile (LDG now, STS after compute)
        float4 pf[5];
        if (kt + 1 < 15) {
            const float4* src = (const float4*)(g_W1t + (kt + 1) * 20 * 128);
#pragma unroll
            for (int i = 0; i < 5; i++) pf[i] = src[i * 128 + tid];
        }
        const float* Bc = Bs[cur];
        int k0 = kt * 20;
#pragma unroll
        for (int kk = 0; kk < 20; kk += 4) {
            F4U2 a4[4];
#pragma unroll
            for (int i = 0; i < 4; i++)
                a4[i].f4 = *(const float4*)&phi_s[(ty * 4 + i) * 304 + k0 + kk];
#pragma unroll
            for (int q = 0; q < 4; q++) {
                F4U2 bq;
                bq.f4 = *(const float4*)&Bc[(kk + q) * 128 + tx * 4];
#pragma unroll
                for (int i = 0; i < 4; i++) {
                    ull aa = dup2(a4[i].f[q]);
                    ffma2(acc[i][0], aa, bq.u2[0]);
                    ffma2(acc[i][1], aa, bq.u2[1]);
                }
            }
        }
        if (kt + 1 < 15) {
            float4* dst = (float4*)Bs[cur ^ 1];
#pragma unroll
            for (int i = 0; i < 5; i++) dst[i * 128 + tid] = pf[i];
        }
    }

#pragma unroll
    for (int i = 0; i < 4; i++) {
        int r = row0 + ty * 4 + i;
        float2 p0 = unpack2(acc[i][0]);
        float2 p1 = unpack2(acc[i][1]);
        float4 o;
        o.x = fmaxf(p0.x, 0.f); o.y = fmaxf(p0.y, 0.f);
        o.z = fmaxf(p1.x, 0.f); o.w = fmaxf(p1.y, 0.f);
        *(float4*)&g_h[(size_t)r * 256 + tx * 4] = o;
    }

    // l_out half: one column per thread (128 threads = 128 cols), 16 rows
    {
        int c = tid;
        float w0 = W2[c * 3 + 0], w1 = W2[c * 3 + 1], w2 = W2[c * 3 + 2];
        float bc = b2[c];
#pragma unroll 4
        for (int r = 0; r < 16; r++) {
            float v = bc + ls[r * 3 + 0] * w0 + ls[r * 3 + 1] * w1 + ls[r * 3 + 2] * w2;
            g_h[(size_t)(row0 + r) * 256 + 128 + c] = fmaxf(v, 0.f);
        }
    }
}

// ------------------------------ output layer --------------------------------
// out = relu(h @ Wc^T + b34)  BM=16, BN=128 (x2 col blocks), BK=16,
// 128 thr, 4x4 f32x2, double-buffered B tiles. grid (B/16, 2).
__global__ void __launch_bounds__(128)
out_kernel(float* __restrict__ out) {
    __shared__ __align__(16) float hs[16 * 256];
    __shared__ __align__(16) float Bs[2][16 * 128];

    int row0 = blockIdx.x * 16, col0 = blockIdx.y * 128;
    int tid = threadIdx.x, tx = tid & 31, ty = tid >> 5;

    {
        const float4* src = (const float4*)(g_h + (size_t)row0 * 256);
        float4* dst = (float4*)hs;
#pragma unroll
        for (int i = 0; i < 8; i++) dst[i * 128 + tid] = src[i * 128 + tid];
    }

    // fill Bs[0] with tile 0: rows k=0..15, cols col0..col0+127
    {
        float4* dst = (float4*)Bs[0];
#pragma unroll
        for (int i = 0; i < 4; i++) {
            int idx = i * 128 + tid;
            int krow = idx >> 5, c = (idx & 31) * 4;
            dst[idx] = *(const float4*)&g_Wct[krow * 256 + col0 + c];
        }
    }

    float4 bb = *(const float4*)&g_b34[col0 + tx * 4];
    ull acc[4][2];
#pragma unroll
    for (int i = 0; i < 4; i++) {
        acc[i][0] = pack2(bb.x, bb.y);
        acc[i][1] = pack2(bb.z, bb.w);
    }

    for (int kt = 0; kt < 16; kt++) {
        __syncthreads();
        int cur = kt & 1;
        float4 pf[4];
        if (kt + 1 < 16) {
            int kbase = (kt + 1) * 16;
#pragma unroll
            for (int i = 0; i < 4; i++) {
                int idx = i * 128 + tid;
                int krow = idx >> 5, c = (idx & 31) * 4;
                pf[i] = *(const float4*)&g_Wct[(kbase + krow) * 256 + col0 + c];
            }
        }
        const float* Bc = Bs[cur];
        int k0 = kt * 16;
#pragma unroll
        for (int kk = 0; kk < 16; kk += 4) {
            F4U2 a4[4];
#pragma unroll
            for (int i = 0; i < 4; i++)
                a4[i].f4 = *(const float4*)&hs[(ty * 4 + i) * 256 + k0 + kk];
#pragma unroll
            for (int q = 0; q < 4; q++) {
                F4U2 bq;
                bq.f4 = *(const float4*)&Bc[(kk + q) * 128 + tx * 4];
#pragma unroll
                for (int i = 0; i < 4; i++) {
                    ull aa = dup2(a4[i].f[q]);
                    ffma2(acc[i][0], aa, bq.u2[0]);
                    ffma2(acc[i][1], aa, bq.u2[1]);
                }
            }
        }
        if (kt + 1 < 16) {
            float4* dst = (float4*)Bs[cur ^ 1];
#pragma unroll
            for (int i = 0; i < 4; i++) dst[i * 128 + tid] = pf[i];
        }
    }

#pragma unroll
    for (int i = 0; i < 4; i++) {
        int r = row0 + ty * 4 + i;
        float2 p0 = unpack2(acc[i][0]);
        float2 p1 = unpack2(acc[i][1]);
        float4 o;
        o.x = fmaxf(p0.x, 0.f); o.y = fmaxf(p0.y, 0.f);
        o.z = fmaxf(p1.x, 0.f); o.w = fmaxf(p1.y, 0.f);
        *(float4*)&out[(size_t)r * 256 + col0 + tx * 4] = o;
    }
}

// ------------------------------ launch --------------------------------------
extern "C" void kernel_launch(void* const* d_in, const int* in_sizes, int n_in,
                              void* d_out, int out_size) {
    const float* x  = (const float*)d_in[0];
    const float* lt = (const float*)d_in[1];
    const float* W1 = (const float*)d_in[2];
    const float* b1 = (const float*)d_in[3];
    const float* W2 = (const float*)d_in[4];
    const float* b2 = (const float*)d_in[5];
    const float* W3 = (const float*)d_in[6];
    const float* b3 = (const float*)d_in[7];
    const float* W4 = (const float*)d_in[8];
    const float* b4 = (const float*)d_in[9];
    float* out = (float*)d_out;

    int B = in_sizes[0] / (3 * P_PTS);
    if (B > MAXB) B = MAXB;

    foveate_kernel<<<B, 512>>>(x, lt, W1, W3, W4, b3, b4);
    hidden_kernel<<<B / 16, 128>>>(lt, b1, W2, b2);
    out_kernel<<<dim3(B / 16, 2), 128>>>(out);
}